// round 3
// baseline (speedup 1.0000x reference)
#include <cuda_runtime.h>

// out[row, f] = x[row, f] * sf^2,  sf = sum_m w_m(t) * coeffs[i-3+m, f]
// i = floor(eig*7.5), t = frac  (uniform knots linspace(0,2,16), cubic
// cardinal B-spline -> exactly 4 nonzero weights).
//
// R3: batch 4 rows per warp-iteration with front-batched LDG.128 (MLP=4-5),
// streaming cache hints on x/out, contiguous 4-row chunks per warp.

#define F_CH 128
#define N_BASES 12
#define PAD_ROWS 18  // padded rows -3..14 -> 0..17; i in [0,14] => i+3 <= 17
#define RPI 4        // rows per warp-iteration

__global__ __launch_bounds__(256, 5)
void spline_filter_kernel(const float* __restrict__ x,
                          const float* __restrict__ eig,
                          const float* __restrict__ coef,
                          float* __restrict__ out,
                          int nrows)
{
    __shared__ float sc[PAD_ROWS * F_CH];  // zero-padded coeff table, 9 KB

    // Cooperative fill: padded rows [0,3) and [15,18) zero, rows 3..14 = coeffs.
    #pragma unroll
    for (int idx = threadIdx.x; idx < PAD_ROWS * F_CH; idx += 256) {
        int j = (idx >> 7) - 3;
        sc[idx] = (j >= 0 && j < N_BASES) ? coef[idx - 3 * F_CH] : 0.0f;
    }
    __syncthreads();

    const int lane    = threadIdx.x & 31;
    const int warp    = (blockIdx.x << 3) + (threadIdx.x >> 5);
    const int wstride = gridDim.x << 3;
    const float* scl  = sc + lane * 4;   // per-lane channel base in smem

    for (int base = warp * RPI; base < nrows; base += wstride * RPI) {
        // ---- front-batched loads: 4 eig + 4 contiguous LDG.128 ----
        float  e[RPI];
        float4 xv[RPI];
        #pragma unroll
        for (int k = 0; k < RPI; k++)
            e[k] = __ldg(eig + base + k);
        #pragma unroll
        for (int k = 0; k < RPI; k++)
            xv[k] = __ldcs((const float4*)(x + (size_t)(base + k) * F_CH) + lane);

        // ---- per-row compute + store ----
        #pragma unroll
        for (int k = 0; k < RPI; k++) {
            float s  = e[k] * 7.5f;
            float fi = floorf(s);
            int   i  = min(max((int)fi, 0), 14);
            float t  = s - (float)i;
            float omt = 1.0f - t;
            float t2  = t * t;
            float w0 = omt * omt * omt * (1.0f / 6.0f);
            float w1 = ((3.0f * t - 6.0f) * t2 + 4.0f) * (1.0f / 6.0f);
            float w2 = (((-3.0f * t + 3.0f) * t + 3.0f) * t + 1.0f) * (1.0f / 6.0f);
            float w3 = t * t2 * (1.0f / 6.0f);

            const float4* p = (const float4*)(scl + i * F_CH);
            float4 a = p[0];       // row i
            float4 b = p[32];      // row i+1  (+512 B)
            float4 c = p[64];      // row i+2  (+1024 B)
            float4 d = p[96];      // row i+3  (+1536 B)

            float4 sf;
            sf.x = w0 * a.x + w1 * b.x + w2 * c.x + w3 * d.x;
            sf.y = w0 * a.y + w1 * b.y + w2 * c.y + w3 * d.y;
            sf.z = w0 * a.z + w1 * b.z + w2 * c.z + w3 * d.z;
            sf.w = w0 * a.w + w1 * b.w + w2 * c.w + w3 * d.w;

            float4 ov;
            ov.x = xv[k].x * sf.x * sf.x;
            ov.y = xv[k].y * sf.y * sf.y;
            ov.z = xv[k].z * sf.z * sf.z;
            ov.w = xv[k].w * sf.w * sf.w;

            __stcs((float4*)(out + (size_t)(base + k) * F_CH) + lane, ov);
        }
    }
}

extern "C" void kernel_launch(void* const* d_in, const int* in_sizes, int n_in,
                              void* d_out, int out_size)
{
    const float* x    = (const float*)d_in[0];  // eval_x        [B,N,128] f32
    const float* eig  = (const float*)d_in[1];  // eval_eigs     [B,N]     f32
    const float* coef = (const float*)d_in[2];  // filter_coeffs [12,128]  f32
    float* out = (float*)d_out;

    int nrows = in_sizes[0] / F_CH;             // B*N = 262144
    // 8 warps/block, 4 rows per warp-iteration; 2048 blocks -> 4 iterations/warp.
    int blocks = (nrows + (64 * RPI) - 1) / (64 * RPI);
    if (blocks > 2048) blocks = 2048;
    spline_filter_kernel<<<blocks, 256>>>(x, eig, coef, out, nrows);
}

// round 5
// speedup vs baseline: 1.0401x; 1.0401x over previous
#include <cuda_runtime.h>

// out[row, f] = x[row, f] * sf^2,  sf = sum_m w_m(t) * coeffs[i-3+m, f]
// i = floor(eig*7.5), t = frac  (uniform knots linspace(0,2,16), cubic
// cardinal B-spline -> exactly 4 nonzero weights).
//
// R4: RPI=2 front-batched loads (2x in-flight bytes/warp vs R2) WITHOUT
// sacrificing occupancy (no minBlocks hint, low register body). 2048 blocks.

#define F_CH 128
#define N_BASES 12
#define PAD_ROWS 18  // padded rows -3..14 -> 0..17; i in [0,14] => i+3 <= 17
#define RPI 2        // rows per warp-iteration

__global__ __launch_bounds__(256)
void spline_filter_kernel(const float* __restrict__ x,
                          const float* __restrict__ eig,
                          const float* __restrict__ coef,
                          float* __restrict__ out,
                          int nrows)
{
    __shared__ float sc[PAD_ROWS * F_CH];  // zero-padded coeff table, 9 KB

    // Cooperative fill: padded rows [0,3) and [15,18) zero, rows 3..14 = coeffs.
    #pragma unroll
    for (int idx = threadIdx.x; idx < PAD_ROWS * F_CH; idx += 256) {
        int j = (idx >> 7) - 3;
        sc[idx] = (j >= 0 && j < N_BASES) ? coef[idx - 3 * F_CH] : 0.0f;
    }
    __syncthreads();

    const int lane    = threadIdx.x & 31;
    const int warp    = (blockIdx.x << 3) + (threadIdx.x >> 5);
    const int wstride = gridDim.x << 3;
    const float* scl  = sc + lane * 4;   // per-lane channel base in smem

    for (int base = warp * RPI; base < nrows; base += wstride * RPI) {
        // ---- front-batched loads: 2 eig + 2 contiguous LDG.128 ----
        float  e0 = __ldg(eig + base);
        float  e1 = __ldg(eig + base + 1);
        float4 xv0 = __ldcs((const float4*)(x + (size_t)base * F_CH) + lane);
        float4 xv1 = __ldcs((const float4*)(x + (size_t)(base + 1) * F_CH) + lane);

        #pragma unroll
        for (int k = 0; k < RPI; k++) {
            float e = (k == 0) ? e0 : e1;
            float4 xv = (k == 0) ? xv0 : xv1;

            float s  = e * 7.5f;
            float fi = floorf(s);
            int   i  = min(max((int)fi, 0), 14);
            float t  = s - (float)i;
            float omt = 1.0f - t;
            float t2  = t * t;
            float w0 = omt * omt * omt * (1.0f / 6.0f);
            float w1 = ((3.0f * t - 6.0f) * t2 + 4.0f) * (1.0f / 6.0f);
            float w2 = (((-3.0f * t + 3.0f) * t + 3.0f) * t + 1.0f) * (1.0f / 6.0f);
            float w3 = t * t2 * (1.0f / 6.0f);

            const float4* p = (const float4*)(scl + i * F_CH);
            float4 a = p[0];       // row i
            float4 b = p[32];      // row i+1  (+512 B)
            float4 c = p[64];      // row i+2  (+1024 B)
            float4 d = p[96];      // row i+3  (+1536 B)

            float4 sf;
            sf.x = w0 * a.x + w1 * b.x + w2 * c.x + w3 * d.x;
            sf.y = w0 * a.y + w1 * b.y + w2 * c.y + w3 * d.y;
            sf.z = w0 * a.z + w1 * b.z + w2 * c.z + w3 * d.z;
            sf.w = w0 * a.w + w1 * b.w + w2 * c.w + w3 * d.w;

            float4 ov;
            ov.x = xv.x * sf.x * sf.x;
            ov.y = xv.y * sf.y * sf.y;
            ov.z = xv.z * sf.z * sf.z;
            ov.w = xv.w * sf.w * sf.w;

            __stcs((float4*)(out + (size_t)(base + k) * F_CH) + lane, ov);
        }
    }
}

extern "C" void kernel_launch(void* const* d_in, const int* in_sizes, int n_in,
                              void* d_out, int out_size)
{
    const float* x    = (const float*)d_in[0];  // eval_x        [B,N,128] f32
    const float* eig  = (const float*)d_in[1];  // eval_eigs     [B,N]     f32
    const float* coef = (const float*)d_in[2];  // filter_coeffs [12,128]  f32
    float* out = (float*)d_out;

    int nrows = in_sizes[0] / F_CH;             // B*N = 262144
    // 8 warps/block, 2 rows per warp-iteration, 2048 blocks
    // -> 8 warp-iterations per warp (fill amortized 16 rows/warp).
    int blocks = 2048;
    int need = (nrows + (8 * RPI) - 1) / (8 * RPI);
    if (blocks > need) blocks = need;
    spline_filter_kernel<<<blocks, 256>>>(x, eig, coef, out, nrows);
}

// round 7
// speedup vs baseline: 1.0692x; 1.0280x over previous
#include <cuda_runtime.h>

// out[row, f] = x[row, f] * sf^2,  sf = sum_m w_m(t) * coeffs[i-3+m, f]
// i = floor(eig*7.5), t = frac  (uniform knots linspace(0,2,16), cubic
// cardinal B-spline -> exactly 4 nonzero weights).
//
// R6: software-pipelined streaming — prefetch next iteration's eig(float2) +
// 2 x-rows while computing/storing the current pair, so GMEM reads stay in
// flight across the LDS/FFMA/STG phase.

#define F_CH 128
#define N_BASES 12
#define PAD_ROWS 18  // padded rows -3..14 -> 0..17; i in [0,14] => i+3 <= 17
#define RPI 2        // rows per warp-iteration (eig loaded as one float2)

__global__ __launch_bounds__(256)
void spline_filter_kernel(const float* __restrict__ x,
                          const float* __restrict__ eig,
                          const float* __restrict__ coef,
                          float* __restrict__ out,
                          int nrows)
{
    __shared__ float sc[PAD_ROWS * F_CH];  // zero-padded coeff table, 9 KB

    // Cooperative fill: padded rows [0,3) and [15,18) zero, rows 3..14 = coeffs.
    #pragma unroll
    for (int idx = threadIdx.x; idx < PAD_ROWS * F_CH; idx += 256) {
        int j = (idx >> 7) - 3;
        sc[idx] = (j >= 0 && j < N_BASES) ? coef[idx - 3 * F_CH] : 0.0f;
    }
    __syncthreads();

    const int lane    = threadIdx.x & 31;
    const int warp    = (blockIdx.x << 3) + (threadIdx.x >> 5);
    const int wstride = gridDim.x << 3;
    const float* scl  = sc + lane * 4;   // per-lane channel base in smem

    int row = warp * RPI;
    if (row >= nrows) return;

    // ---- prologue: load iteration 0 ----
    float2 e  = *(const float2*)(eig + row);       // row even -> 8B aligned
    float4 xa = __ldcs((const float4*)(x + (size_t)row * F_CH) + lane);
    float4 xb = __ldcs((const float4*)(x + (size_t)(row + 1) * F_CH) + lane);

    while (true) {
        const int nrow = row + wstride * RPI;
        const bool nvalid = nrow < nrows;

        // ---- prefetch next iteration (independent of current compute) ----
        float2 ne;
        float4 nxa, nxb;
        if (nvalid) {
            ne  = *(const float2*)(eig + nrow);
            nxa = __ldcs((const float4*)(x + (size_t)nrow * F_CH) + lane);
            nxb = __ldcs((const float4*)(x + (size_t)(nrow + 1) * F_CH) + lane);
        }

        // ---- compute + store current pair ----
        #pragma unroll
        for (int k = 0; k < RPI; k++) {
            float ev  = (k == 0) ? e.x : e.y;
            float4 xv = (k == 0) ? xa  : xb;

            float s  = ev * 7.5f;
            float fi = floorf(s);
            int   i  = min(max((int)fi, 0), 14);
            float t  = s - (float)i;
            float omt = 1.0f - t;
            float t2  = t * t;
            float w0 = omt * omt * omt * (1.0f / 6.0f);
            float w1 = ((3.0f * t - 6.0f) * t2 + 4.0f) * (1.0f / 6.0f);
            float w2 = (((-3.0f * t + 3.0f) * t + 3.0f) * t + 1.0f) * (1.0f / 6.0f);
            float w3 = t * t2 * (1.0f / 6.0f);

            const float4* p = (const float4*)(scl + i * F_CH);
            float4 a = p[0];       // row i
            float4 b = p[32];      // row i+1  (+512 B)
            float4 c = p[64];      // row i+2  (+1024 B)
            float4 d = p[96];      // row i+3  (+1536 B)

            float4 sf;
            sf.x = w0 * a.x + w1 * b.x + w2 * c.x + w3 * d.x;
            sf.y = w0 * a.y + w1 * b.y + w2 * c.y + w3 * d.y;
            sf.z = w0 * a.z + w1 * b.z + w2 * c.z + w3 * d.z;
            sf.w = w0 * a.w + w1 * b.w + w2 * c.w + w3 * d.w;

            float4 ov;
            ov.x = xv.x * sf.x * sf.x;
            ov.y = xv.y * sf.y * sf.y;
            ov.z = xv.z * sf.z * sf.z;
            ov.w = xv.w * sf.w * sf.w;

            __stcs((float4*)(out + (size_t)(row + k) * F_CH) + lane, ov);
        }

        if (!nvalid) break;
        e = ne; xa = nxa; xb = nxb; row = nrow;
    }
}

extern "C" void kernel_launch(void* const* d_in, const int* in_sizes, int n_in,
                              void* d_out, int out_size)
{
    const float* x    = (const float*)d_in[0];  // eval_x        [B,N,128] f32
    const float* eig  = (const float*)d_in[1];  // eval_eigs     [B,N]     f32
    const float* coef = (const float*)d_in[2];  // filter_coeffs [12,128]  f32
    float* out = (float*)d_out;

    int nrows = in_sizes[0] / F_CH;             // B*N = 262144
    // 8 warps/block, 2 rows per warp-iteration, 2048 blocks
    // -> 8 pipelined iterations per warp.
    int blocks = 2048;
    int need = (nrows + (8 * RPI) - 1) / (8 * RPI);
    if (blocks > need) blocks = need;
    spline_filter_kernel<<<blocks, 256>>>(x, eig, coef, out, nrows);
}